// round 1
// baseline (speedup 1.0000x reference)
#include <cuda_runtime.h>

namespace {
constexpr int NTOK = 4096;   // 16*16*16 spatial tokens
constexpr int CDIM = 256;
}

// Scratch (allocation-free rule: __device__ globals)
__device__ float g_xn[CDIM * NTOK];        // 4 MB
__device__ float g_qkv[3 * CDIM * NTOK];   // 12 MB
__device__ float g_h[CDIM * NTOK];         // 4 MB

// ---------------------------------------------------------------------------
// GroupNorm: 16 groups, each 16 channels x 4096 tokens = 65536 elems
// ---------------------------------------------------------------------------
__global__ __launch_bounds__(256) void gn_kernel(
    const float* __restrict__ x, const float* __restrict__ gamma,
    const float* __restrict__ beta, float* __restrict__ xn)
{
    const int g = blockIdx.x;
    const int GSZ = 16 * NTOK;
    const float4* xg = reinterpret_cast<const float4*>(x + g * GSZ);
    float s = 0.f, s2 = 0.f;
    for (int i = threadIdx.x; i < GSZ / 4; i += 256) {
        float4 v = xg[i];
        s  += v.x + v.y + v.z + v.w;
        s2 += v.x * v.x + v.y * v.y + v.z * v.z + v.w * v.w;
    }
    #pragma unroll
    for (int o = 16; o; o >>= 1) {
        s  += __shfl_xor_sync(0xffffffffu, s, o);
        s2 += __shfl_xor_sync(0xffffffffu, s2, o);
    }
    __shared__ float red1[8], red2[8];
    __shared__ float mu_s, rstd_s;
    if ((threadIdx.x & 31) == 0) { red1[threadIdx.x >> 5] = s; red2[threadIdx.x >> 5] = s2; }
    __syncthreads();
    if (threadIdx.x == 0) {
        float ts = 0.f, ts2 = 0.f;
        #pragma unroll
        for (int i = 0; i < 8; i++) { ts += red1[i]; ts2 += red2[i]; }
        float mu = ts / (float)GSZ;
        float var = ts2 / (float)GSZ - mu * mu;
        mu_s = mu;
        rstd_s = rsqrtf(var + 1e-5f);
    }
    __syncthreads();
    const float mu = mu_s, rstd = rstd_s;
    float4* xo = reinterpret_cast<float4*>(xn + g * GSZ);
    for (int i = threadIdx.x; i < GSZ / 4; i += 256) {
        int c = g * 16 + (i >> 10);          // 1024 float4 per channel row
        float ga = gamma[c] * rstd;
        float be = beta[c] - mu * ga;
        float4 v = xg[i];
        v.x = v.x * ga + be; v.y = v.y * ga + be;
        v.z = v.z * ga + be; v.w = v.w * ga + be;
        xo[i] = v;
    }
}

// ---------------------------------------------------------------------------
// SGEMM: C[M,N] = A[M,K] @ B[K,N], 64x64 block tile, 4x4 per thread, BK=16.
// EPI=true adds bias[m] + resid[m*N+n] (projection + residual).
// ---------------------------------------------------------------------------
template<bool EPI>
__global__ __launch_bounds__(256) void sgemm64(
    const float* __restrict__ A, const float* __restrict__ B,
    float* __restrict__ C, int M, int N, int K,
    const float* __restrict__ bias, const float* __restrict__ resid)
{
    __shared__ float As[16][68];   // [k][m], pitch 68 keeps float4 reads aligned
    __shared__ float Bs[16][64];   // [k][n]
    const int tid = threadIdx.x;
    const int tx = tid & 15, ty = tid >> 4;
    const int m0 = blockIdx.y * 64, n0 = blockIdx.x * 64;
    const int ar = tid >> 2, ac = (tid & 3) * 4;      // A tile 64x16
    const int brow = tid >> 4, bcol = (tid & 15) * 4; // B tile 16x64
    float acc[4][4] = {};
    for (int k0 = 0; k0 < K; k0 += 16) {
        float4 av = *reinterpret_cast<const float4*>(&A[(m0 + ar) * K + k0 + ac]);
        float4 bv = *reinterpret_cast<const float4*>(&B[(size_t)(k0 + brow) * N + n0 + bcol]);
        As[ac + 0][ar] = av.x; As[ac + 1][ar] = av.y;
        As[ac + 2][ar] = av.z; As[ac + 3][ar] = av.w;
        *reinterpret_cast<float4*>(&Bs[brow][bcol]) = bv;
        __syncthreads();
        #pragma unroll
        for (int kk = 0; kk < 16; kk++) {
            float4 a = *reinterpret_cast<const float4*>(&As[kk][ty * 4]);
            float4 b = *reinterpret_cast<const float4*>(&Bs[kk][tx * 4]);
            acc[0][0] += a.x*b.x; acc[0][1] += a.x*b.y; acc[0][2] += a.x*b.z; acc[0][3] += a.x*b.w;
            acc[1][0] += a.y*b.x; acc[1][1] += a.y*b.y; acc[1][2] += a.y*b.z; acc[1][3] += a.y*b.w;
            acc[2][0] += a.z*b.x; acc[2][1] += a.z*b.y; acc[2][2] += a.z*b.z; acc[2][3] += a.z*b.w;
            acc[3][0] += a.w*b.x; acc[3][1] += a.w*b.y; acc[3][2] += a.w*b.z; acc[3][3] += a.w*b.w;
        }
        __syncthreads();
    }
    #pragma unroll
    for (int i = 0; i < 4; i++) {
        int m = m0 + ty * 4 + i;
        float bi = EPI ? bias[m] : 0.f;
        #pragma unroll
        for (int j = 0; j < 4; j++) {
            int n = n0 + tx * 4 + j;
            float v = acc[i][j] + bi;
            if (EPI) v += resid[(size_t)m * N + n];
            C[(size_t)m * N + n] = v;
        }
    }
}

// ---------------------------------------------------------------------------
// Flash attention, fp32. One block = (head, 64-query tile). 256 threads.
// q/k/v layout from qkv buffer: row (hd*192 + c), c<64 q, 64..127 k, 128..191 v.
// S tile 64x32 per key step; online softmax with quad (4-thread) row reduce.
// ---------------------------------------------------------------------------
__global__ __launch_bounds__(256) void attn_kernel(
    const float* __restrict__ qkv, float* __restrict__ hout)
{
    const int hd = blockIdx.y;
    const int t0 = blockIdx.x * 64;
    const float* qp = qkv + (size_t)(hd * 192) * NTOK;
    const float* kp = qp + (size_t)64 * NTOK;
    const float* vp = kp + (size_t)64 * NTOK;

    __shared__ float Qs[64][68];   // [c][t], pre-scaled by 1/8
    __shared__ float Ks[64][36];   // [c][s]
    __shared__ float Vt[32][68];   // [s][c]
    __shared__ float Ss[64][36];   // [t][s] scores -> probs
    __shared__ float row_m[64], row_l[64], row_alpha[64];

    const int tid = threadIdx.x;
    const int tx = tid & 15, ty = tid >> 4;

    for (int i = tid; i < 64 * 16; i += 256) {
        int c = i >> 4, t4 = (i & 15) << 2;
        float4 v = *reinterpret_cast<const float4*>(&qp[(size_t)c * NTOK + t0 + t4]);
        Qs[c][t4 + 0] = v.x * 0.125f; Qs[c][t4 + 1] = v.y * 0.125f;
        Qs[c][t4 + 2] = v.z * 0.125f; Qs[c][t4 + 3] = v.w * 0.125f;
    }
    if (tid < 64) { row_m[tid] = -1e30f; row_l[tid] = 0.f; }
    float o[4][4] = {};

    for (int s0 = 0; s0 < NTOK; s0 += 32) {
        __syncthreads();   // protects Ks/Vt/Ss reuse + first-iter Qs/row_m visibility
        for (int i = tid; i < 64 * 8; i += 256) {
            int c = i >> 3, s4 = (i & 7) << 2;
            float4 kv = *reinterpret_cast<const float4*>(&kp[(size_t)c * NTOK + s0 + s4]);
            Ks[c][s4 + 0] = kv.x; Ks[c][s4 + 1] = kv.y;
            Ks[c][s4 + 2] = kv.z; Ks[c][s4 + 3] = kv.w;
            float4 vv = *reinterpret_cast<const float4*>(&vp[(size_t)c * NTOK + s0 + s4]);
            Vt[s4 + 0][c] = vv.x; Vt[s4 + 1][c] = vv.y;
            Vt[s4 + 2][c] = vv.z; Vt[s4 + 3][c] = vv.w;
        }
        __syncthreads();

        // S = (Q/8)^T K : thread computes 4 t-rows x 2 s-cols
        {
            float sa[4][2] = {};
            #pragma unroll
            for (int c = 0; c < 64; c++) {
                float4 a = *reinterpret_cast<const float4*>(&Qs[c][ty * 4]);
                float2 b = *reinterpret_cast<const float2*>(&Ks[c][tx * 2]);
                sa[0][0] += a.x * b.x; sa[0][1] += a.x * b.y;
                sa[1][0] += a.y * b.x; sa[1][1] += a.y * b.y;
                sa[2][0] += a.z * b.x; sa[2][1] += a.z * b.y;
                sa[3][0] += a.w * b.x; sa[3][1] += a.w * b.y;
            }
            #pragma unroll
            for (int i = 0; i < 4; i++) {
                float2 w2; w2.x = sa[i][0]; w2.y = sa[i][1];
                *reinterpret_cast<float2*>(&Ss[ty * 4 + i][tx * 2]) = w2;
            }
        }
        __syncthreads();

        // online softmax on the 64x32 tile: 4 threads per row
        {
            const int r = tid >> 2, sub = tid & 3;
            float mloc = -1e30f;
            #pragma unroll
            for (int j = 0; j < 8; j++) mloc = fmaxf(mloc, Ss[r][sub + 4 * j]);
            mloc = fmaxf(mloc, __shfl_xor_sync(0xffffffffu, mloc, 1));
            mloc = fmaxf(mloc, __shfl_xor_sync(0xffffffffu, mloc, 2));
            const float mold = row_m[r];
            const float mnew = fmaxf(mold, mloc);
            float sloc = 0.f;
            #pragma unroll
            for (int j = 0; j < 8; j++) {
                float p = __expf(Ss[r][sub + 4 * j] - mnew);
                Ss[r][sub + 4 * j] = p;
                sloc += p;
            }
            sloc += __shfl_xor_sync(0xffffffffu, sloc, 1);
            sloc += __shfl_xor_sync(0xffffffffu, sloc, 2);
            if (sub == 0) {
                float alpha = __expf(mold - mnew);
                row_alpha[r] = alpha;
                row_l[r] = row_l[r] * alpha + sloc;
                row_m[r] = mnew;
            }
        }
        __syncthreads();

        // O rescale + O += P @ V
        {
            float al0 = row_alpha[ty * 4 + 0];
            float al1 = row_alpha[ty * 4 + 1];
            float al2 = row_alpha[ty * 4 + 2];
            float al3 = row_alpha[ty * 4 + 3];
            #pragma unroll
            for (int j = 0; j < 4; j++) {
                o[0][j] *= al0; o[1][j] *= al1; o[2][j] *= al2; o[3][j] *= al3;
            }
            #pragma unroll
            for (int s = 0; s < 32; s++) {
                float p0 = Ss[ty * 4 + 0][s];
                float p1 = Ss[ty * 4 + 1][s];
                float p2 = Ss[ty * 4 + 2][s];
                float p3 = Ss[ty * 4 + 3][s];
                float4 v = *reinterpret_cast<const float4*>(&Vt[s][tx * 4]);
                o[0][0] += p0 * v.x; o[0][1] += p0 * v.y; o[0][2] += p0 * v.z; o[0][3] += p0 * v.w;
                o[1][0] += p1 * v.x; o[1][1] += p1 * v.y; o[1][2] += p1 * v.z; o[1][3] += p1 * v.w;
                o[2][0] += p2 * v.x; o[2][1] += p2 * v.y; o[2][2] += p2 * v.z; o[2][3] += p2 * v.w;
                o[3][0] += p3 * v.x; o[3][1] += p3 * v.y; o[3][2] += p3 * v.z; o[3][3] += p3 * v.w;
            }
        }
    }

    const float l0 = 1.f / row_l[ty * 4 + 0];
    const float l1 = 1.f / row_l[ty * 4 + 1];
    const float l2 = 1.f / row_l[ty * 4 + 2];
    const float l3 = 1.f / row_l[ty * 4 + 3];
    #pragma unroll
    for (int j = 0; j < 4; j++) {
        int c = hd * 64 + tx * 4 + j;
        float* hp = hout + (size_t)c * NTOK + t0;
        hp[ty * 4 + 0] = o[0][j] * l0;
        hp[ty * 4 + 1] = o[1][j] * l1;
        hp[ty * 4 + 2] = o[2][j] * l2;
        hp[ty * 4 + 3] = o[3][j] * l3;
    }
}

// ---------------------------------------------------------------------------
extern "C" void kernel_launch(void* const* d_in, const int* in_sizes, int n_in,
                              void* d_out, int out_size)
{
    const float* x      = (const float*)d_in[0];
    const float* gamma  = (const float*)d_in[1];
    const float* beta   = (const float*)d_in[2];
    const float* w_qkv  = (const float*)d_in[3];
    const float* w_proj = (const float*)d_in[4];
    const float* b_proj = (const float*)d_in[5];
    float* out = (float*)d_out;

    float *xn, *qkv, *h;
    cudaGetSymbolAddress((void**)&xn,  g_xn);
    cudaGetSymbolAddress((void**)&qkv, g_qkv);
    cudaGetSymbolAddress((void**)&h,   g_h);

    gn_kernel<<<16, 256>>>(x, gamma, beta, xn);
    sgemm64<false><<<dim3(NTOK / 64, 12), 256>>>(w_qkv, xn, qkv, 768, NTOK, CDIM,
                                                 nullptr, nullptr);
    attn_kernel<<<dim3(NTOK / 64, 4), 256>>>(qkv, h);
    sgemm64<true><<<dim3(NTOK / 64, 4), 256>>>(w_proj, h, out, CDIM, NTOK, CDIM,
                                               b_proj, x);
}

// round 2
// speedup vs baseline: 2.9488x; 2.9488x over previous
#include <cuda_runtime.h>

namespace {
constexpr int NTOK = 4096;   // 16*16*16 tokens
constexpr int CDIM = 256;
constexpr int ATT_SMEM = (64 * 72 + 64 * 72 + 64 * 68) * 4;  // QP + K + V
}

// Scratch (allocation-free rule: __device__ globals)
__device__ float g_xn[CDIM * NTOK];
__device__ float g_qkv[3 * CDIM * NTOK];
__device__ float g_h[CDIM * NTOK];

__device__ __forceinline__ unsigned f2tf(float f) {
    unsigned u;
    asm("cvt.rna.tf32.f32 %0, %1;" : "=r"(u) : "f"(f));
    return u;
}

__device__ __forceinline__ void mma8(float* c, const unsigned* a, unsigned b0, unsigned b1) {
    asm volatile(
        "mma.sync.aligned.m16n8k8.row.col.f32.tf32.tf32.f32 "
        "{%0,%1,%2,%3},{%4,%5,%6,%7},{%8,%9},{%0,%1,%2,%3};\n"
        : "+f"(c[0]), "+f"(c[1]), "+f"(c[2]), "+f"(c[3])
        : "r"(a[0]), "r"(a[1]), "r"(a[2]), "r"(a[3]), "r"(b0), "r"(b1));
}

// ---------------------------------------------------------------------------
// GroupNorm (exact fp32)
// ---------------------------------------------------------------------------
__global__ __launch_bounds__(256) void gn_kernel(
    const float* __restrict__ x, const float* __restrict__ gamma,
    const float* __restrict__ beta, float* __restrict__ xn)
{
    const int g = blockIdx.x;
    const int GSZ = 16 * NTOK;
    const float4* xg = reinterpret_cast<const float4*>(x + g * GSZ);
    float s = 0.f, s2 = 0.f;
    for (int i = threadIdx.x; i < GSZ / 4; i += 256) {
        float4 v = xg[i];
        s  += v.x + v.y + v.z + v.w;
        s2 += v.x * v.x + v.y * v.y + v.z * v.z + v.w * v.w;
    }
    #pragma unroll
    for (int o = 16; o; o >>= 1) {
        s  += __shfl_xor_sync(0xffffffffu, s, o);
        s2 += __shfl_xor_sync(0xffffffffu, s2, o);
    }
    __shared__ float red1[8], red2[8];
    __shared__ float mu_s, rstd_s;
    if ((threadIdx.x & 31) == 0) { red1[threadIdx.x >> 5] = s; red2[threadIdx.x >> 5] = s2; }
    __syncthreads();
    if (threadIdx.x == 0) {
        float ts = 0.f, ts2 = 0.f;
        #pragma unroll
        for (int i = 0; i < 8; i++) { ts += red1[i]; ts2 += red2[i]; }
        float mu = ts / (float)GSZ;
        float var = ts2 / (float)GSZ - mu * mu;
        mu_s = mu;
        rstd_s = rsqrtf(var + 1e-5f);
    }
    __syncthreads();
    const float mu = mu_s, rstd = rstd_s;
    float4* xo = reinterpret_cast<float4*>(xn + g * GSZ);
    for (int i = threadIdx.x; i < GSZ / 4; i += 256) {
        int c = g * 16 + (i >> 10);
        float ga = gamma[c] * rstd;
        float be = beta[c] - mu * ga;
        float4 v = xg[i];
        v.x = v.x * ga + be; v.y = v.y * ga + be;
        v.z = v.z * ga + be; v.w = v.w * ga + be;
        xo[i] = v;
    }
}

// ---------------------------------------------------------------------------
// tf32 GEMM: C[M,N] = A[M,K] @ B[K,N]; block tile 64x128, BK=32, 8 warps.
// Warp = 32x32 (2 m-tiles x 4 n-tiles of m16n8). EPI adds bias[m] + resid.
// ---------------------------------------------------------------------------
template<bool EPI>
__global__ __launch_bounds__(256) void gemm_tf32(
    const float* __restrict__ A, const float* __restrict__ B,
    float* __restrict__ C, int M, int N, int K,
    const float* __restrict__ bias, const float* __restrict__ resid)
{
    __shared__ unsigned As[64 * 36];    // [m][k] pitch 36 (=4 mod 32)
    __shared__ unsigned Bs[32 * 136];   // [k][n] pitch 136 (=8 mod 32)
    const int tid = threadIdx.x, lane = tid & 31, wid = tid >> 5;
    const int g = lane >> 2, tg = lane & 3;
    const int wm = wid >> 2, wn = wid & 3;
    const int m0 = blockIdx.y * 64, n0 = blockIdx.x * 128;
    const int ar = tid >> 2, ac = (tid & 3) * 8;
    const int br = tid >> 3, bc = (tid & 7) * 16;
    float acc[2][4][4] = {};

    for (int k0 = 0; k0 < K; k0 += 32) {
        {
            float4 a0v = *(const float4*)&A[(size_t)(m0 + ar) * K + k0 + ac];
            float4 a1v = *(const float4*)&A[(size_t)(m0 + ar) * K + k0 + ac + 4];
            unsigned* ap = &As[ar * 36 + ac];
            ap[0] = f2tf(a0v.x); ap[1] = f2tf(a0v.y); ap[2] = f2tf(a0v.z); ap[3] = f2tf(a0v.w);
            ap[4] = f2tf(a1v.x); ap[5] = f2tf(a1v.y); ap[6] = f2tf(a1v.z); ap[7] = f2tf(a1v.w);
            #pragma unroll
            for (int j = 0; j < 4; j++) {
                float4 bv = *(const float4*)&B[(size_t)(k0 + br) * N + n0 + bc + 4 * j];
                unsigned* bp = &Bs[br * 136 + bc + 4 * j];
                bp[0] = f2tf(bv.x); bp[1] = f2tf(bv.y); bp[2] = f2tf(bv.z); bp[3] = f2tf(bv.w);
            }
        }
        __syncthreads();
        #pragma unroll
        for (int kk = 0; kk < 4; kk++) {
            unsigned af[2][4];
            #pragma unroll
            for (int mt = 0; mt < 2; mt++) {
                int r = (wm * 32 + mt * 16 + g) * 36 + kk * 8 + tg;
                af[mt][0] = As[r];
                af[mt][1] = As[r + 8 * 36];
                af[mt][2] = As[r + 4];
                af[mt][3] = As[r + 8 * 36 + 4];
            }
            #pragma unroll
            for (int nt = 0; nt < 4; nt++) {
                unsigned b0 = Bs[(kk * 8 + tg) * 136 + wn * 32 + nt * 8 + g];
                unsigned b1 = Bs[(kk * 8 + tg + 4) * 136 + wn * 32 + nt * 8 + g];
                mma8(acc[0][nt], af[0], b0, b1);
                mma8(acc[1][nt], af[1], b0, b1);
            }
        }
        __syncthreads();
    }

    #pragma unroll
    for (int mt = 0; mt < 2; mt++) {
        int mA = m0 + wm * 32 + mt * 16 + g;
        int mB = mA + 8;
        float biA = EPI ? bias[mA] : 0.f;
        float biB = EPI ? bias[mB] : 0.f;
        #pragma unroll
        for (int nt = 0; nt < 4; nt++) {
            int n = n0 + wn * 32 + nt * 8 + 2 * tg;
            float v0 = acc[mt][nt][0] + biA;
            float v1 = acc[mt][nt][1] + biA;
            float v2 = acc[mt][nt][2] + biB;
            float v3 = acc[mt][nt][3] + biB;
            if (EPI) {
                v0 += resid[(size_t)mA * N + n];
                v1 += resid[(size_t)mA * N + n + 1];
                v2 += resid[(size_t)mB * N + n];
                v3 += resid[(size_t)mB * N + n + 1];
            }
            C[(size_t)mA * N + n]     = v0;
            C[(size_t)mA * N + n + 1] = v1;
            C[(size_t)mB * N + n]     = v2;
            C[(size_t)mB * N + n + 1] = v3;
        }
    }
}

// ---------------------------------------------------------------------------
// Flash attention with tf32 mma. Block = (64-query tile, head), 4 warps.
// SMEM tiles staged in tf32. QP buffer aliased: Q[d][t] first, then P[s][t].
// ---------------------------------------------------------------------------
__global__ void __launch_bounds__(128, 2) attn_tc(
    const float* __restrict__ qkv, float* __restrict__ hout)
{
    extern __shared__ unsigned sm[];
    unsigned* QP = sm;                 // 64 x 72  (Q[d][t], later P[s][t])
    unsigned* Ks = sm + 64 * 72;       // 64 x 72  K[d][key]
    unsigned* Vs = sm + 2 * 64 * 72;   // 64 x 68  V[d][key]

    const int hd = blockIdx.y, t0 = blockIdx.x * 64;
    const float* qp = qkv + (size_t)(hd * 192) * NTOK;
    const float* kp = qp + (size_t)64 * NTOK;
    const float* vp = kp + (size_t)64 * NTOK;

    const int tid = threadIdx.x, lane = tid & 31, wid = tid >> 5;
    const int g = lane >> 2, tg = lane & 3;
    const int m0 = wid * 16;

    // stage Q (scaled by 1/8), layout [d][t] pitch 72
    for (int i = tid; i < 64 * 16; i += 128) {
        int c = i >> 4, t4 = (i & 15) << 2;
        float4 v = *(const float4*)&qp[(size_t)c * NTOK + t0 + t4];
        unsigned* q = &QP[c * 72 + t4];
        q[0] = f2tf(v.x * 0.125f); q[1] = f2tf(v.y * 0.125f);
        q[2] = f2tf(v.z * 0.125f); q[3] = f2tf(v.w * 0.125f);
    }
    __syncthreads();

    unsigned qa[8][4];
    #pragma unroll
    for (int k = 0; k < 8; k++) {
        qa[k][0] = QP[(k * 8 + tg) * 72 + m0 + g];
        qa[k][1] = QP[(k * 8 + tg) * 72 + m0 + g + 8];
        qa[k][2] = QP[(k * 8 + tg + 4) * 72 + m0 + g];
        qa[k][3] = QP[(k * 8 + tg + 4) * 72 + m0 + g + 8];
    }

    float oacc[8][4] = {};
    float mrow0 = -1e30f, mrow1 = -1e30f, lrow0 = 0.f, lrow1 = 0.f;

    for (int s0 = 0; s0 < NTOK; s0 += 64) {
        __syncthreads();    // prior PV reads done (and Q frag loads on iter 0)
        for (int i = tid; i < 64 * 16; i += 128) {
            int c = i >> 4, s4 = (i & 15) << 2;
            float4 kv = *(const float4*)&kp[(size_t)c * NTOK + s0 + s4];
            unsigned* kd = &Ks[c * 72 + s4];
            kd[0] = f2tf(kv.x); kd[1] = f2tf(kv.y); kd[2] = f2tf(kv.z); kd[3] = f2tf(kv.w);
            float4 vv = *(const float4*)&vp[(size_t)c * NTOK + s0 + s4];
            unsigned* vd = &Vs[c * 68 + s4];
            vd[0] = f2tf(vv.x); vd[1] = f2tf(vv.y); vd[2] = f2tf(vv.z); vd[3] = f2tf(vv.w);
        }
        __syncthreads();

        // S = Q K^T  (64x64 per block, 16x64 per warp)
        float sacc[8][4] = {};
        #pragma unroll
        for (int k = 0; k < 8; k++) {
            #pragma unroll
            for (int n = 0; n < 8; n++) {
                unsigned b0 = Ks[(k * 8 + tg) * 72 + n * 8 + g];
                unsigned b1 = Ks[(k * 8 + tg + 4) * 72 + n * 8 + g];
                mma8(sacc[n], qa[k], b0, b1);
            }
        }

        // online softmax: rows g (c0,c1) and g+8 (c2,c3), quad-reduced
        float ml0 = -1e30f, ml1 = -1e30f;
        #pragma unroll
        for (int n = 0; n < 8; n++) {
            ml0 = fmaxf(ml0, fmaxf(sacc[n][0], sacc[n][1]));
            ml1 = fmaxf(ml1, fmaxf(sacc[n][2], sacc[n][3]));
        }
        ml0 = fmaxf(ml0, __shfl_xor_sync(0xffffffffu, ml0, 1));
        ml0 = fmaxf(ml0, __shfl_xor_sync(0xffffffffu, ml0, 2));
        ml1 = fmaxf(ml1, __shfl_xor_sync(0xffffffffu, ml1, 1));
        ml1 = fmaxf(ml1, __shfl_xor_sync(0xffffffffu, ml1, 2));
        float mn0 = fmaxf(mrow0, ml0), mn1 = fmaxf(mrow1, ml1);
        float al0 = __expf(mrow0 - mn0), al1 = __expf(mrow1 - mn1);
        float sum0 = 0.f, sum1 = 0.f;
        #pragma unroll
        for (int n = 0; n < 8; n++) {
            float p0 = __expf(sacc[n][0] - mn0);
            float p1 = __expf(sacc[n][1] - mn0);
            float p2 = __expf(sacc[n][2] - mn1);
            float p3 = __expf(sacc[n][3] - mn1);
            sacc[n][0] = p0; sacc[n][1] = p1; sacc[n][2] = p2; sacc[n][3] = p3;
            sum0 += p0 + p1; sum1 += p2 + p3;
        }
        sum0 += __shfl_xor_sync(0xffffffffu, sum0, 1);
        sum0 += __shfl_xor_sync(0xffffffffu, sum0, 2);
        sum1 += __shfl_xor_sync(0xffffffffu, sum1, 1);
        sum1 += __shfl_xor_sync(0xffffffffu, sum1, 2);
        lrow0 = lrow0 * al0 + sum0;
        lrow1 = lrow1 * al1 + sum1;
        mrow0 = mn0; mrow1 = mn1;
        #pragma unroll
        for (int n = 0; n < 8; n++) {
            oacc[n][0] *= al0; oacc[n][1] *= al0;
            oacc[n][2] *= al1; oacc[n][3] *= al1;
        }

        // store P tiles to QP as P[s][t] (pitch 72), own columns only
        #pragma unroll
        for (int n = 0; n < 8; n++) {
            int sC = n * 8 + 2 * tg;
            QP[sC * 72 + m0 + g]           = f2tf(sacc[n][0]);
            QP[(sC + 1) * 72 + m0 + g]     = f2tf(sacc[n][1]);
            QP[sC * 72 + m0 + g + 8]       = f2tf(sacc[n][2]);
            QP[(sC + 1) * 72 + m0 + g + 8] = f2tf(sacc[n][3]);
        }
        __syncwarp();

        // O += P V   (P: m16 x k8 tiles over s;  V: k8 x n8 over d)
        #pragma unroll
        for (int k = 0; k < 8; k++) {
            unsigned pa[4];
            pa[0] = QP[(k * 8 + tg) * 72 + m0 + g];
            pa[1] = QP[(k * 8 + tg) * 72 + m0 + g + 8];
            pa[2] = QP[(k * 8 + tg + 4) * 72 + m0 + g];
            pa[3] = QP[(k * 8 + tg + 4) * 72 + m0 + g + 8];
            #pragma unroll
            for (int n = 0; n < 8; n++) {
                unsigned b0 = Vs[(n * 8 + g) * 68 + k * 8 + tg];
                unsigned b1 = Vs[(n * 8 + g) * 68 + k * 8 + tg + 4];
                mma8(oacc[n], pa, b0, b1);
            }
        }
    }

    const float li0 = 1.f / lrow0, li1 = 1.f / lrow1;
    #pragma unroll
    for (int n = 0; n < 8; n++) {
        int c = hd * 64 + n * 8 + 2 * tg;
        size_t base = (size_t)c * NTOK + t0 + m0 + g;
        hout[base]            = oacc[n][0] * li0;
        hout[base + NTOK]     = oacc[n][1] * li0;
        hout[base + 8]        = oacc[n][2] * li1;
        hout[base + NTOK + 8] = oacc[n][3] * li1;
    }
}

// ---------------------------------------------------------------------------
extern "C" void kernel_launch(void* const* d_in, const int* in_sizes, int n_in,
                              void* d_out, int out_size)
{
    const float* x      = (const float*)d_in[0];
    const float* gamma  = (const float*)d_in[1];
    const float* beta   = (const float*)d_in[2];
    const float* w_qkv  = (const float*)d_in[3];
    const float* w_proj = (const float*)d_in[4];
    const float* b_proj = (const float*)d_in[5];
    float* out = (float*)d_out;

    float *xn, *qkv, *h;
    cudaGetSymbolAddress((void**)&xn,  g_xn);
    cudaGetSymbolAddress((void**)&qkv, g_qkv);
    cudaGetSymbolAddress((void**)&h,   g_h);

    cudaFuncSetAttribute(attn_tc, cudaFuncAttributeMaxDynamicSharedMemorySize, ATT_SMEM);

    gn_kernel<<<16, 256>>>(x, gamma, beta, xn);
    gemm_tf32<false><<<dim3(NTOK / 128, 768 / 64), 256>>>(w_qkv, xn, qkv,
                                                          768, NTOK, CDIM, nullptr, nullptr);
    attn_tc<<<dim3(NTOK / 64, 4), 128, ATT_SMEM>>>(qkv, h);
    gemm_tf32<true><<<dim3(NTOK / 128, CDIM / 64), 256>>>(w_proj, h, out,
                                                          CDIM, NTOK, CDIM, b_proj, x);
}

// round 3
// speedup vs baseline: 3.5158x; 1.1923x over previous
#include <cuda_runtime.h>

namespace {
constexpr int NTOK = 4096;
constexpr int CDIM = 256;
constexpr int ATT_SMEM = (64 * 72 + 2 * 64 * 72 + 2 * 64 * 68) * 4;   // 90112 B
constexpr int GEMM_SMEM = (2 * 64 * 36 + 2 * 32 * 136) * 4;           // 53248 B
}

// Scratch (allocation-free rule: __device__ globals). tf32 payloads as unsigned.
__device__ unsigned g_xn[CDIM * NTOK];
__device__ unsigned g_qkv[3 * CDIM * NTOK];
__device__ unsigned g_h[CDIM * NTOK];
__device__ unsigned g_wq[3 * CDIM * CDIM];
__device__ unsigned g_wp[CDIM * CDIM];
__device__ float2   g_part[128];            // groupnorm partial sums

__device__ __forceinline__ unsigned f2tf(float f) {
    unsigned u;
    asm("cvt.rna.tf32.f32 %0, %1;" : "=r"(u) : "f"(f));
    return u;
}
__device__ __forceinline__ unsigned saddr(const void* p) {
    return (unsigned)__cvta_generic_to_shared(p);
}
__device__ __forceinline__ void cpa16(unsigned dst, const void* src) {
    asm volatile("cp.async.cg.shared.global [%0], [%1], 16;\n" :: "r"(dst), "l"(src));
}
#define CP_COMMIT() asm volatile("cp.async.commit_group;\n" ::)
#define CP_WAIT0()  asm volatile("cp.async.wait_group 0;\n" ::)
#define CP_WAIT1()  asm volatile("cp.async.wait_group 1;\n" ::)

__device__ __forceinline__ void mma8(float* c, const unsigned* a, unsigned b0, unsigned b1) {
    asm volatile(
        "mma.sync.aligned.m16n8k8.row.col.f32.tf32.tf32.f32 "
        "{%0,%1,%2,%3},{%4,%5,%6,%7},{%8,%9},{%0,%1,%2,%3};\n"
        : "+f"(c[0]), "+f"(c[1]), "+f"(c[2]), "+f"(c[3])
        : "r"(a[0]), "r"(a[1]), "r"(a[2]), "r"(a[3]), "r"(b0), "r"(b1));
}

// ---------------------------------------------------------------------------
// fp32 -> tf32 bit conversion (weights), grid-stride
// ---------------------------------------------------------------------------
__global__ __launch_bounds__(256) void cvt_kernel(
    const float* __restrict__ s, unsigned* __restrict__ d, int n)
{
    for (int i = blockIdx.x * 256 + threadIdx.x; i < n; i += gridDim.x * 256)
        d[i] = f2tf(s[i]);
}

// ---------------------------------------------------------------------------
// GroupNorm phase 1: partial sums. Block = (group g, slice s): 8192 elems.
// ---------------------------------------------------------------------------
__global__ __launch_bounds__(256) void gn_stats(const float* __restrict__ x)
{
    const int b = blockIdx.x;               // 0..127 : g*8 + slice
    const float4* xg = reinterpret_cast<const float4*>(x) + (size_t)b * 2048;
    float s = 0.f, s2 = 0.f;
    for (int i = threadIdx.x; i < 2048; i += 256) {
        float4 v = xg[i];
        s  += v.x + v.y + v.z + v.w;
        s2 += v.x * v.x + v.y * v.y + v.z * v.z + v.w * v.w;
    }
    #pragma unroll
    for (int o = 16; o; o >>= 1) {
        s  += __shfl_xor_sync(0xffffffffu, s, o);
        s2 += __shfl_xor_sync(0xffffffffu, s2, o);
    }
    __shared__ float r1[8], r2[8];
    if ((threadIdx.x & 31) == 0) { r1[threadIdx.x >> 5] = s; r2[threadIdx.x >> 5] = s2; }
    __syncthreads();
    if (threadIdx.x == 0) {
        float ts = 0.f, ts2 = 0.f;
        #pragma unroll
        for (int i = 0; i < 8; i++) { ts += r1[i]; ts2 += r2[i]; }
        g_part[b] = make_float2(ts, ts2);
    }
}

// ---------------------------------------------------------------------------
// GroupNorm phase 2: normalize + affine, write tf32
// ---------------------------------------------------------------------------
__global__ __launch_bounds__(256) void gn_apply(
    const float* __restrict__ x, const float* __restrict__ gamma,
    const float* __restrict__ beta, unsigned* __restrict__ xn)
{
    const int i0 = blockIdx.x * 256 + threadIdx.x;          // f4 index, 262144 total
    for (int i = i0; i < 262144; i += gridDim.x * 256) {
        int c = i >> 10;
        int g = c >> 4;
        float ts = 0.f, ts2 = 0.f;
        #pragma unroll
        for (int j = 0; j < 8; j++) { float2 p = g_part[g * 8 + j]; ts += p.x; ts2 += p.y; }
        const float inv = 1.f / 65536.f;
        float mu = ts * inv;
        float rstd = rsqrtf(ts2 * inv - mu * mu + 1e-5f);
        float ga = gamma[c] * rstd;
        float be = beta[c] - mu * ga;
        float4 v = reinterpret_cast<const float4*>(x)[i];
        uint4 o;
        o.x = f2tf(v.x * ga + be); o.y = f2tf(v.y * ga + be);
        o.z = f2tf(v.z * ga + be); o.w = f2tf(v.w * ga + be);
        reinterpret_cast<uint4*>(xn)[i] = o;
    }
}

// ---------------------------------------------------------------------------
// tf32 GEMM, preconverted inputs, cp.async double-buffered.
// C[M,N] = A[M,K] @ B[K,N]; tile 64x128, BK=32, 8 warps.
// EPI=false: write tf32 bits with q-scale (rows m%192<64 get *0.125).
// EPI=true : write float with bias[m] + resid[m*N+n].
// ---------------------------------------------------------------------------
template<bool EPI>
__global__ __launch_bounds__(256) void gemm_pre(
    const unsigned* __restrict__ A, const unsigned* __restrict__ B,
    void* __restrict__ Cout, int M, int N, int K,
    const float* __restrict__ bias, const float* __restrict__ resid)
{
    extern __shared__ unsigned gsm[];
    unsigned* As = gsm;                  // 2 x [64][36]
    unsigned* Bs = gsm + 2 * 64 * 36;    // 2 x [32][136]

    const int tid = threadIdx.x, lane = tid & 31, wid = tid >> 5;
    const int g = lane >> 2, tg = lane & 3;
    const int wm = wid >> 2, wn = wid & 3;
    const int m0 = blockIdx.y * 64, n0 = blockIdx.x * 128;
    const int ar = tid >> 2, acq = (tid & 3) * 8;
    const int br = tid >> 3, bcq = (tid & 7) * 16;

    float acc[2][4][4] = {};

    auto issue = [&](int k0, int buf) {
        unsigned* Ad = As + buf * 64 * 36;
        unsigned* Bd = Bs + buf * 32 * 136;
        #pragma unroll
        for (int j = 0; j < 2; j++)
            cpa16(saddr(&Ad[ar * 36 + acq + 4 * j]),
                  &A[(size_t)(m0 + ar) * K + k0 + acq + 4 * j]);
        #pragma unroll
        for (int j = 0; j < 4; j++)
            cpa16(saddr(&Bd[br * 136 + bcq + 4 * j]),
                  &B[(size_t)(k0 + br) * N + n0 + bcq + 4 * j]);
    };

    issue(0, 0);
    CP_COMMIT();
    const int NKI = K / 32;
    for (int i = 0; i < NKI; i++) {
        if (i + 1 < NKI) { issue(32 * (i + 1), (i + 1) & 1); CP_COMMIT(); CP_WAIT1(); }
        else             { CP_WAIT0(); }
        __syncthreads();
        const unsigned* Ab = As + (i & 1) * 64 * 36;
        const unsigned* Bb = Bs + (i & 1) * 32 * 136;
        #pragma unroll
        for (int kk = 0; kk < 4; kk++) {
            unsigned af[2][4];
            #pragma unroll
            for (int mt = 0; mt < 2; mt++) {
                int r = (wm * 32 + mt * 16 + g) * 36 + kk * 8 + tg;
                af[mt][0] = Ab[r];
                af[mt][1] = Ab[r + 8 * 36];
                af[mt][2] = Ab[r + 4];
                af[mt][3] = Ab[r + 8 * 36 + 4];
            }
            #pragma unroll
            for (int nt = 0; nt < 4; nt++) {
                unsigned b0 = Bb[(kk * 8 + tg) * 136 + wn * 32 + nt * 8 + g];
                unsigned b1 = Bb[(kk * 8 + tg + 4) * 136 + wn * 32 + nt * 8 + g];
                mma8(acc[0][nt], af[0], b0, b1);
                mma8(acc[1][nt], af[1], b0, b1);
            }
        }
        __syncthreads();
    }

    #pragma unroll
    for (int mt = 0; mt < 2; mt++) {
        int mA = m0 + wm * 32 + mt * 16 + g;
        int mB = mA + 8;
        if (EPI) {
            float* C = (float*)Cout;
            float biA = bias[mA], biB = bias[mB];
            #pragma unroll
            for (int nt = 0; nt < 4; nt++) {
                int n = n0 + wn * 32 + nt * 8 + 2 * tg;
                C[(size_t)mA * N + n]     = acc[mt][nt][0] + biA + resid[(size_t)mA * N + n];
                C[(size_t)mA * N + n + 1] = acc[mt][nt][1] + biA + resid[(size_t)mA * N + n + 1];
                C[(size_t)mB * N + n]     = acc[mt][nt][2] + biB + resid[(size_t)mB * N + n];
                C[(size_t)mB * N + n + 1] = acc[mt][nt][3] + biB + resid[(size_t)mB * N + n + 1];
            }
        } else {
            unsigned* C = (unsigned*)Cout;
            float sc = ((mA / 64) % 3 == 0) ? 0.125f : 1.0f;   // q rows pre-scaled
            #pragma unroll
            for (int nt = 0; nt < 4; nt++) {
                int n = n0 + wn * 32 + nt * 8 + 2 * tg;
                C[(size_t)mA * N + n]     = f2tf(acc[mt][nt][0] * sc);
                C[(size_t)mA * N + n + 1] = f2tf(acc[mt][nt][1] * sc);
                C[(size_t)mB * N + n]     = f2tf(acc[mt][nt][2] * sc);
                C[(size_t)mB * N + n + 1] = f2tf(acc[mt][nt][3] * sc);
            }
        }
    }
}

// ---------------------------------------------------------------------------
// Flash attention, tf32 mma, cp.async double-buffered K/V, preconverted qkv.
// Block = (64-query tile, head), 4 warps. h written as tf32.
// ---------------------------------------------------------------------------
__global__ void __launch_bounds__(128, 2) attn_tc(
    const unsigned* __restrict__ qkv, unsigned* __restrict__ hout)
{
    extern __shared__ unsigned sm[];
    unsigned* QP = sm;                       // [64][72]: Q[d][t] then P[s][t]
    unsigned* Ksb = sm + 64 * 72;            // 2 x [64][72]
    unsigned* Vsb = sm + 64 * 72 + 2 * 64 * 72;  // 2 x [64][68]

    const int hd = blockIdx.y, t0 = blockIdx.x * 64;
    const unsigned* qp = qkv + (size_t)(hd * 192) * NTOK;
    const unsigned* kp = qp + (size_t)64 * NTOK;
    const unsigned* vp = kp + (size_t)64 * NTOK;

    const int tid = threadIdx.x, lane = tid & 31, wid = tid >> 5;
    const int g = lane >> 2, tg = lane & 3;
    const int m0 = wid * 16;

    // stage Q (already scaled by 1/8 in qkv-gemm epilogue)
    for (int i = tid; i < 1024; i += 128) {
        int c = i >> 4, t4 = (i & 15) << 2;
        cpa16(saddr(&QP[c * 72 + t4]), &qp[(size_t)c * NTOK + t0 + t4]);
    }
    CP_COMMIT();

    auto issueKV = (void(*)())nullptr; (void)issueKV;
    {   // KV tile 0
        for (int i = tid; i < 1024; i += 128) {
            int c = i >> 4, s4 = (i & 15) << 2;
            cpa16(saddr(&Ksb[c * 72 + s4]), &kp[(size_t)c * NTOK + s4]);
            cpa16(saddr(&Vsb[c * 68 + s4]), &vp[(size_t)c * NTOK + s4]);
        }
        CP_COMMIT();
    }

    CP_WAIT1();          // Q resident (KV0 may still fly)
    __syncthreads();

    unsigned qa[8][4];
    #pragma unroll
    for (int k = 0; k < 8; k++) {
        qa[k][0] = QP[(k * 8 + tg) * 72 + m0 + g];
        qa[k][1] = QP[(k * 8 + tg) * 72 + m0 + g + 8];
        qa[k][2] = QP[(k * 8 + tg + 4) * 72 + m0 + g];
        qa[k][3] = QP[(k * 8 + tg + 4) * 72 + m0 + g + 8];
    }

    float oacc[8][4] = {};
    float mrow0 = -1e30f, mrow1 = -1e30f, lrow0 = 0.f, lrow1 = 0.f;

    for (int it = 0; it < 64; it++) {
        if (it < 63) {
            int s0 = (it + 1) * 64, buf = (it + 1) & 1;
            unsigned* Kd = Ksb + buf * 64 * 72;
            unsigned* Vd = Vsb + buf * 64 * 68;
            for (int i = tid; i < 1024; i += 128) {
                int c = i >> 4, s4 = (i & 15) << 2;
                cpa16(saddr(&Kd[c * 72 + s4]), &kp[(size_t)c * NTOK + s0 + s4]);
                cpa16(saddr(&Vd[c * 68 + s4]), &vp[(size_t)c * NTOK + s0 + s4]);
            }
            CP_COMMIT();
            CP_WAIT1();
        } else {
            CP_WAIT0();
        }
        __syncthreads();
        const unsigned* Ks = Ksb + (it & 1) * 64 * 72;
        const unsigned* Vs = Vsb + (it & 1) * 64 * 68;

        // S = Q K^T
        float sacc[8][4] = {};
        #pragma unroll
        for (int k = 0; k < 8; k++) {
            #pragma unroll
            for (int n = 0; n < 8; n++) {
                unsigned b0 = Ks[(k * 8 + tg) * 72 + n * 8 + g];
                unsigned b1 = Ks[(k * 8 + tg + 4) * 72 + n * 8 + g];
                mma8(sacc[n], qa[k], b0, b1);
            }
        }

        // online softmax
        float ml0 = -1e30f, ml1 = -1e30f;
        #pragma unroll
        for (int n = 0; n < 8; n++) {
            ml0 = fmaxf(ml0, fmaxf(sacc[n][0], sacc[n][1]));
            ml1 = fmaxf(ml1, fmaxf(sacc[n][2], sacc[n][3]));
        }
        ml0 = fmaxf(ml0, __shfl_xor_sync(0xffffffffu, ml0, 1));
        ml0 = fmaxf(ml0, __shfl_xor_sync(0xffffffffu, ml0, 2));
        ml1 = fmaxf(ml1, __shfl_xor_sync(0xffffffffu, ml1, 1));
        ml1 = fmaxf(ml1, __shfl_xor_sync(0xffffffffu, ml1, 2));
        float mn0 = fmaxf(mrow0, ml0), mn1 = fmaxf(mrow1, ml1);
        float al0 = __expf(mrow0 - mn0), al1 = __expf(mrow1 - mn1);
        float sum0 = 0.f, sum1 = 0.f;
        #pragma unroll
        for (int n = 0; n < 8; n++) {
            float p0 = __expf(sacc[n][0] - mn0);
            float p1 = __expf(sacc[n][1] - mn0);
            float p2 = __expf(sacc[n][2] - mn1);
            float p3 = __expf(sacc[n][3] - mn1);
            sacc[n][0] = p0; sacc[n][1] = p1; sacc[n][2] = p2; sacc[n][3] = p3;
            sum0 += p0 + p1; sum1 += p2 + p3;
        }
        sum0 += __shfl_xor_sync(0xffffffffu, sum0, 1);
        sum0 += __shfl_xor_sync(0xffffffffu, sum0, 2);
        sum1 += __shfl_xor_sync(0xffffffffu, sum1, 1);
        sum1 += __shfl_xor_sync(0xffffffffu, sum1, 2);
        lrow0 = lrow0 * al0 + sum0;
        lrow1 = lrow1 * al1 + sum1;
        mrow0 = mn0; mrow1 = mn1;
        #pragma unroll
        for (int n = 0; n < 8; n++) {
            oacc[n][0] *= al0; oacc[n][1] *= al0;
            oacc[n][2] *= al1; oacc[n][3] *= al1;
        }

        // P -> QP (own warp columns only)
        #pragma unroll
        for (int n = 0; n < 8; n++) {
            int sC = n * 8 + 2 * tg;
            QP[sC * 72 + m0 + g]           = f2tf(sacc[n][0]);
            QP[(sC + 1) * 72 + m0 + g]     = f2tf(sacc[n][1]);
            QP[sC * 72 + m0 + g + 8]       = f2tf(sacc[n][2]);
            QP[(sC + 1) * 72 + m0 + g + 8] = f2tf(sacc[n][3]);
        }
        __syncwarp();

        // O += P V
        #pragma unroll
        for (int k = 0; k < 8; k++) {
            unsigned pa[4];
            pa[0] = QP[(k * 8 + tg) * 72 + m0 + g];
            pa[1] = QP[(k * 8 + tg) * 72 + m0 + g + 8];
            pa[2] = QP[(k * 8 + tg + 4) * 72 + m0 + g];
            pa[3] = QP[(k * 8 + tg + 4) * 72 + m0 + g + 8];
            #pragma unroll
            for (int n = 0; n < 8; n++) {
                unsigned b0 = Vs[(n * 8 + g) * 68 + k * 8 + tg];
                unsigned b1 = Vs[(n * 8 + g) * 68 + k * 8 + tg + 4];
                mma8(oacc[n], pa, b0, b1);
            }
        }
        __syncthreads();
    }

    const float li0 = 1.f / lrow0, li1 = 1.f / lrow1;
    #pragma unroll
    for (int n = 0; n < 8; n++) {
        int c = hd * 64 + n * 8 + 2 * tg;
        size_t base = (size_t)c * NTOK + t0 + m0 + g;
        hout[base]            = f2tf(oacc[n][0] * li0);
        hout[base + NTOK]     = f2tf(oacc[n][1] * li0);
        hout[base + 8]        = f2tf(oacc[n][2] * li1);
        hout[base + NTOK + 8] = f2tf(oacc[n][3] * li1);
    }
}

// ---------------------------------------------------------------------------
extern "C" void kernel_launch(void* const* d_in, const int* in_sizes, int n_in,
                              void* d_out, int out_size)
{
    const float* x      = (const float*)d_in[0];
    const float* gamma  = (const float*)d_in[1];
    const float* beta   = (const float*)d_in[2];
    const float* w_qkv  = (const float*)d_in[3];
    const float* w_proj = (const float*)d_in[4];
    const float* b_proj = (const float*)d_in[5];
    float* out = (float*)d_out;

    unsigned *xn, *qkv, *h, *wq, *wp;
    cudaGetSymbolAddress((void**)&xn,  g_xn);
    cudaGetSymbolAddress((void**)&qkv, g_qkv);
    cudaGetSymbolAddress((void**)&h,   g_h);
    cudaGetSymbolAddress((void**)&wq,  g_wq);
    cudaGetSymbolAddress((void**)&wp,  g_wp);

    static bool attr_done = false;
    if (!attr_done) {
        cudaFuncSetAttribute(attn_tc, cudaFuncAttributeMaxDynamicSharedMemorySize, ATT_SMEM);
        cudaFuncSetAttribute(gemm_pre<false>, cudaFuncAttributeMaxDynamicSharedMemorySize, GEMM_SMEM);
        cudaFuncSetAttribute(gemm_pre<true>,  cudaFuncAttributeMaxDynamicSharedMemorySize, GEMM_SMEM);
        attr_done = true;
    }

    cvt_kernel<<<192, 256>>>(w_qkv, wq, 3 * CDIM * CDIM);
    cvt_kernel<<<64, 256>>>(w_proj, wp, CDIM * CDIM);
    gn_stats<<<128, 256>>>(x);
    gn_apply<<<256, 256>>>(x, gamma, beta, xn);
    gemm_pre<false><<<dim3(NTOK / 128, 768 / 64), 256, GEMM_SMEM>>>(
        wq, xn, qkv, 768, NTOK, CDIM, nullptr, nullptr);
    attn_tc<<<dim3(NTOK / 64, 4), 128, ATT_SMEM>>>(qkv, h);
    gemm_pre<true><<<dim3(NTOK / 128, CDIM / 64), 256, GEMM_SMEM>>>(
        wp, h, out, CDIM, NTOK, CDIM, b_proj, x);
}

// round 4
// speedup vs baseline: 6.4537x; 1.8356x over previous
#include <cuda_runtime.h>
#include <cuda_fp16.h>

namespace {
constexpr int NTOK = 4096;
constexpr int CDIM = 256;
constexpr int ATT_SMEM  = (64 * 72 + 2 * 64 * 72 + 2 * 64 * 72) * 2;   // 46080 B
constexpr int GEMM_SMEM = (2 * 64 * 56 + 2 * 32 * 136) * 2;            // 31744 B
}

// Scratch (allocation-free rule: __device__ globals)
__device__ __half g_xn[CDIM * NTOK];
__device__ __half g_qkv[3 * CDIM * NTOK];
__device__ __half g_h[CDIM * NTOK];
__device__ __half g_wq[3 * CDIM * CDIM];
__device__ __half g_wp[CDIM * CDIM];
__device__ float2 g_part[128];

__device__ __forceinline__ unsigned saddr(const void* p) {
    return (unsigned)__cvta_generic_to_shared(p);
}
__device__ __forceinline__ void cpa16(unsigned dst, const void* src) {
    asm volatile("cp.async.cg.shared.global [%0], [%1], 16;\n" :: "r"(dst), "l"(src));
}
#define CP_COMMIT() asm volatile("cp.async.commit_group;\n" ::)
#define CP_WAIT0()  asm volatile("cp.async.wait_group 0;\n" ::)
#define CP_WAIT1()  asm volatile("cp.async.wait_group 1;\n" ::)

__device__ __forceinline__ unsigned h2u(__half2 h) {
    return *reinterpret_cast<unsigned*>(&h);
}
__device__ __forceinline__ void mma16(float* c, const unsigned* a, unsigned b0, unsigned b1) {
    asm volatile(
        "mma.sync.aligned.m16n8k16.row.col.f32.f16.f16.f32 "
        "{%0,%1,%2,%3},{%4,%5,%6,%7},{%8,%9},{%0,%1,%2,%3};\n"
        : "+f"(c[0]), "+f"(c[1]), "+f"(c[2]), "+f"(c[3])
        : "r"(a[0]), "r"(a[1]), "r"(a[2]), "r"(a[3]), "r"(b0), "r"(b1));
}
__device__ __forceinline__ void ldm4(unsigned* r, unsigned a) {
    asm volatile("ldmatrix.sync.aligned.m8n8.x4.shared.b16 {%0,%1,%2,%3}, [%4];\n"
        : "=r"(r[0]), "=r"(r[1]), "=r"(r[2]), "=r"(r[3]) : "r"(a));
}
__device__ __forceinline__ void ldm4t(unsigned* r, unsigned a) {
    asm volatile("ldmatrix.sync.aligned.m8n8.x4.trans.shared.b16 {%0,%1,%2,%3}, [%4];\n"
        : "=r"(r[0]), "=r"(r[1]), "=r"(r[2]), "=r"(r[3]) : "r"(a));
}

// ---------------------------------------------------------------------------
// fp32 -> fp16 weight conversion
// ---------------------------------------------------------------------------
__global__ __launch_bounds__(256) void cvt_h(
    const float* __restrict__ s, __half* __restrict__ d, int n)
{
    for (int i = blockIdx.x * 256 + threadIdx.x; i < n / 2; i += gridDim.x * 256) {
        float2 v = reinterpret_cast<const float2*>(s)[i];
        reinterpret_cast<__half2*>(d)[i] = __floats2half2_rn(v.x, v.y);
    }
}

// ---------------------------------------------------------------------------
// GroupNorm phase 1: partial sums (fp32 exact)
// ---------------------------------------------------------------------------
__global__ __launch_bounds__(256) void gn_stats(const float* __restrict__ x)
{
    const int b = blockIdx.x;               // g*8 + slice
    const float4* xg = reinterpret_cast<const float4*>(x) + (size_t)b * 2048;
    float s = 0.f, s2 = 0.f;
    for (int i = threadIdx.x; i < 2048; i += 256) {
        float4 v = xg[i];
        s  += v.x + v.y + v.z + v.w;
        s2 += v.x * v.x + v.y * v.y + v.z * v.z + v.w * v.w;
    }
    #pragma unroll
    for (int o = 16; o; o >>= 1) {
        s  += __shfl_xor_sync(0xffffffffu, s, o);
        s2 += __shfl_xor_sync(0xffffffffu, s2, o);
    }
    __shared__ float r1[8], r2[8];
    if ((threadIdx.x & 31) == 0) { r1[threadIdx.x >> 5] = s; r2[threadIdx.x >> 5] = s2; }
    __syncthreads();
    if (threadIdx.x == 0) {
        float ts = 0.f, ts2 = 0.f;
        #pragma unroll
        for (int i = 0; i < 8; i++) { ts += r1[i]; ts2 += r2[i]; }
        g_part[b] = make_float2(ts, ts2);
    }
}

// ---------------------------------------------------------------------------
// GroupNorm phase 2: normalize + affine, write fp16
// ---------------------------------------------------------------------------
__global__ __launch_bounds__(256) void gn_apply(
    const float* __restrict__ x, const float* __restrict__ gamma,
    const float* __restrict__ beta, __half* __restrict__ xn)
{
    for (int i = blockIdx.x * 256 + threadIdx.x; i < 262144; i += gridDim.x * 256) {
        int c = i >> 10;
        int g = c >> 4;
        float ts = 0.f, ts2 = 0.f;
        #pragma unroll
        for (int j = 0; j < 8; j++) { float2 p = g_part[g * 8 + j]; ts += p.x; ts2 += p.y; }
        const float inv = 1.f / 65536.f;
        float mu = ts * inv;
        float rstd = rsqrtf(ts2 * inv - mu * mu + 1e-5f);
        float ga = gamma[c] * rstd;
        float be = beta[c] - mu * ga;
        float4 v = reinterpret_cast<const float4*>(x)[i];
        uint2 o;
        o.x = h2u(__floats2half2_rn(v.x * ga + be, v.y * ga + be));
        o.y = h2u(__floats2half2_rn(v.z * ga + be, v.w * ga + be));
        reinterpret_cast<uint2*>(xn)[i] = o;
    }
}

// ---------------------------------------------------------------------------
// fp16 GEMM: C[M,N] = A[M,K] @ B[K,N]; tile 64x128, BK=32, 8 warps.
// A [m][k] pitch 56 (ldm4 non-trans), B [k][n] pitch 136 (ldm4 trans).
// EPI=false: half out with q-scale (rows with (m/64)%3==0 get *0.125).
// EPI=true : float out with bias[m] + resid[m*N+n].
// ---------------------------------------------------------------------------
template<bool EPI>
__global__ __launch_bounds__(256) void gemm_h(
    const __half* __restrict__ A, const __half* __restrict__ B,
    void* __restrict__ Cout, int M, int N, int K,
    const float* __restrict__ bias, const float* __restrict__ resid)
{
    extern __shared__ __half gsm[];
    __half* As = gsm;                  // 2 x [64][56]
    __half* Bs = gsm + 2 * 64 * 56;    // 2 x [32][136]

    const int tid = threadIdx.x, lane = tid & 31, wid = tid >> 5;
    const int g = lane >> 2, tg = lane & 3;
    const int wm = wid >> 2, wn = wid & 3;
    const int m0 = blockIdx.y * 64, n0 = blockIdx.x * 128;
    const int ar = tid >> 2, acq = (tid & 3) * 8;     // A: 4 chunks/row
    const int br = tid >> 4, bcq = (tid & 15) * 8;    // B: 16 chunks/row, 2 rows/thread
    float acc[2][4][4] = {};

    auto issue = [&](int k0, int buf) {
        __half* Ad = As + buf * 64 * 56;
        __half* Bd = Bs + buf * 32 * 136;
        cpa16(saddr(&Ad[ar * 56 + acq]), &A[(size_t)(m0 + ar) * K + k0 + acq]);
        cpa16(saddr(&Bd[br * 136 + bcq]), &B[(size_t)(k0 + br) * N + n0 + bcq]);
        cpa16(saddr(&Bd[(br + 16) * 136 + bcq]), &B[(size_t)(k0 + br + 16) * N + n0 + bcq]);
    };

    issue(0, 0);
    CP_COMMIT();
    const int NKI = K / 32;
    for (int i = 0; i < NKI; i++) {
        if (i + 1 < NKI) { issue(32 * (i + 1), (i + 1) & 1); CP_COMMIT(); CP_WAIT1(); }
        else             { CP_WAIT0(); }
        __syncthreads();
        const __half* Ab = As + (i & 1) * 64 * 56;
        const __half* Bb = Bs + (i & 1) * 32 * 136;
        #pragma unroll
        for (int ks = 0; ks < 2; ks++) {
            const int k0 = ks * 16;
            unsigned af[2][4];
            #pragma unroll
            for (int mt = 0; mt < 2; mt++)
                ldm4(af[mt], saddr(&Ab[(wm * 32 + mt * 16 + (lane & 15)) * 56
                                        + k0 + (lane >> 4) * 8]));
            unsigned bf[2][4];
            #pragma unroll
            for (int np = 0; np < 2; np++)
                ldm4t(bf[np], saddr(&Bb[(k0 + (lane & 15)) * 136
                                         + wn * 32 + np * 16 + ((lane & 16) >> 1)]));
            #pragma unroll
            for (int mt = 0; mt < 2; mt++)
                #pragma unroll
                for (int np = 0; np < 2; np++) {
                    mma16(acc[mt][np * 2],     af[mt], bf[np][0], bf[np][1]);
                    mma16(acc[mt][np * 2 + 1], af[mt], bf[np][2], bf[np][3]);
                }
        }
        __syncthreads();
    }

    #pragma unroll
    for (int mt = 0; mt < 2; mt++) {
        int mA = m0 + wm * 32 + mt * 16 + g;
        int mB = mA + 8;
        if (EPI) {
            float* C = (float*)Cout;
            float biA = bias[mA], biB = bias[mB];
            #pragma unroll
            for (int nt = 0; nt < 4; nt++) {
                int n = n0 + wn * 32 + nt * 8 + 2 * tg;
                C[(size_t)mA * N + n]     = acc[mt][nt][0] + biA + resid[(size_t)mA * N + n];
                C[(size_t)mA * N + n + 1] = acc[mt][nt][1] + biA + resid[(size_t)mA * N + n + 1];
                C[(size_t)mB * N + n]     = acc[mt][nt][2] + biB + resid[(size_t)mB * N + n];
                C[(size_t)mB * N + n + 1] = acc[mt][nt][3] + biB + resid[(size_t)mB * N + n + 1];
            }
        } else {
            __half* C = (__half*)Cout;
            float sc = ((mA / 64) % 3 == 0) ? 0.125f : 1.0f;   // pre-scale q rows
            #pragma unroll
            for (int nt = 0; nt < 4; nt++) {
                int n = n0 + wn * 32 + nt * 8 + 2 * tg;
                C[(size_t)mA * N + n]     = __float2half(acc[mt][nt][0] * sc);
                C[(size_t)mA * N + n + 1] = __float2half(acc[mt][nt][1] * sc);
                C[(size_t)mB * N + n]     = __float2half(acc[mt][nt][2] * sc);
                C[(size_t)mB * N + n + 1] = __float2half(acc[mt][nt][3] * sc);
            }
        }
    }
}

// ---------------------------------------------------------------------------
// Flash attention, fp16 mma + ldmatrix, P in registers, cp.async K/V pipeline.
// Block = (64-query tile, head), 4 warps. Tiles [d][t]/[d][s] pitch 72.
// ---------------------------------------------------------------------------
__global__ void __launch_bounds__(128, 3) attn_h(
    const __half* __restrict__ qkv, __half* __restrict__ hout)
{
    extern __shared__ __half sm[];
    __half* Qs  = sm;                  // [64][72]
    __half* Ksb = sm + 64 * 72;        // 2 x [64][72]
    __half* Vsb = sm + 3 * 64 * 72;    // 2 x [64][72]

    const int hd = blockIdx.y, t0 = blockIdx.x * 64;
    const __half* qp = qkv + (size_t)(hd * 192) * NTOK;
    const __half* kp = qp + (size_t)64 * NTOK;
    const __half* vp = kp + (size_t)64 * NTOK;

    const int tid = threadIdx.x, lane = tid & 31, wid = tid >> 5;
    const int g = lane >> 2, tg = lane & 3;
    const int m0 = wid * 16;

    for (int i = tid; i < 512; i += 128) {
        int c = i >> 3, t8 = (i & 7) * 8;
        cpa16(saddr(&Qs[c * 72 + t8]), &qp[(size_t)c * NTOK + t0 + t8]);
    }
    CP_COMMIT();
    for (int i = tid; i < 512; i += 128) {
        int c = i >> 3, s8 = (i & 7) * 8;
        cpa16(saddr(&Ksb[c * 72 + s8]), &kp[(size_t)c * NTOK + s8]);
        cpa16(saddr(&Vsb[c * 72 + s8]), &vp[(size_t)c * NTOK + s8]);
    }
    CP_COMMIT();
    CP_WAIT1();            // Q resident
    __syncthreads();

    // Q A-fragments (trans from [d][t] storage), 4 k16 steps over d
    unsigned qa[4][4];
    {
        const int krow = (lane & 7) + ((lane & 16) >> 1);
        const int mcol = m0 + (lane & 8);
        #pragma unroll
        for (int ks = 0; ks < 4; ks++)
            ldm4t(qa[ks], saddr(&Qs[(ks * 16 + krow) * 72 + mcol]));
    }

    float oacc[8][4] = {};
    float mrow0 = -1e30f, mrow1 = -1e30f, lrow0 = 0.f, lrow1 = 0.f;

    for (int it = 0; it < 64; it++) {
        if (it < 63) {
            const int s0 = (it + 1) * 64, buf = (it + 1) & 1;
            __half* Kd = Ksb + buf * 64 * 72;
            __half* Vd = Vsb + buf * 64 * 72;
            for (int i = tid; i < 512; i += 128) {
                int c = i >> 3, s8 = (i & 7) * 8;
                cpa16(saddr(&Kd[c * 72 + s8]), &kp[(size_t)c * NTOK + s0 + s8]);
                cpa16(saddr(&Vd[c * 72 + s8]), &vp[(size_t)c * NTOK + s0 + s8]);
            }
            CP_COMMIT();
            CP_WAIT1();
        } else {
            CP_WAIT0();
        }
        __syncthreads();
        const __half* Ks = Ksb + (it & 1) * 64 * 72;
        const __half* Vs = Vsb + (it & 1) * 64 * 72;

        // S = Q K^T : B-frags trans from K [d][s]
        float sacc[8][4] = {};
        #pragma unroll
        for (int ks = 0; ks < 4; ks++) {
            #pragma unroll
            for (int np = 0; np < 4; np++) {
                unsigned bf[4];
                ldm4t(bf, saddr(&Ks[(ks * 16 + (lane & 15)) * 72
                                     + np * 16 + ((lane & 16) >> 1)]));
                mma16(sacc[np * 2],     qa[ks], bf[0], bf[1]);
                mma16(sacc[np * 2 + 1], qa[ks], bf[2], bf[3]);
            }
        }

        // online softmax (rows g -> c0/c1, g+8 -> c2/c3; quad reduce)
        float ml0 = -1e30f, ml1 = -1e30f;
        #pragma unroll
        for (int n = 0; n < 8; n++) {
            ml0 = fmaxf(ml0, fmaxf(sacc[n][0], sacc[n][1]));
            ml1 = fmaxf(ml1, fmaxf(sacc[n][2], sacc[n][3]));
        }
        ml0 = fmaxf(ml0, __shfl_xor_sync(0xffffffffu, ml0, 1));
        ml0 = fmaxf(ml0, __shfl_xor_sync(0xffffffffu, ml0, 2));
        ml1 = fmaxf(ml1, __shfl_xor_sync(0xffffffffu, ml1, 1));
        ml1 = fmaxf(ml1, __shfl_xor_sync(0xffffffffu, ml1, 2));
        float mn0 = fmaxf(mrow0, ml0), mn1 = fmaxf(mrow1, ml1);
        float al0 = __expf(mrow0 - mn0), al1 = __expf(mrow1 - mn1);
        float sum0 = 0.f, sum1 = 0.f;
        #pragma unroll
        for (int n = 0; n < 8; n++) {
            float p0 = __expf(sacc[n][0] - mn0);
            float p1 = __expf(sacc[n][1] - mn0);
            float p2 = __expf(sacc[n][2] - mn1);
            float p3 = __expf(sacc[n][3] - mn1);
            sacc[n][0] = p0; sacc[n][1] = p1; sacc[n][2] = p2; sacc[n][3] = p3;
            sum0 += p0 + p1; sum1 += p2 + p3;
        }
        sum0 += __shfl_xor_sync(0xffffffffu, sum0, 1);
        sum0 += __shfl_xor_sync(0xffffffffu, sum0, 2);
        sum1 += __shfl_xor_sync(0xffffffffu, sum1, 1);
        sum1 += __shfl_xor_sync(0xffffffffu, sum1, 2);
        lrow0 = lrow0 * al0 + sum0;
        lrow1 = lrow1 * al1 + sum1;
        mrow0 = mn0; mrow1 = mn1;
        #pragma unroll
        for (int n = 0; n < 8; n++) {
            oacc[n][0] *= al0; oacc[n][1] *= al0;
            oacc[n][2] *= al1; oacc[n][3] *= al1;
        }

        // O += P V : P A-frags straight from sacc registers (C-layout == A-layout)
        #pragma unroll
        for (int ks = 0; ks < 4; ks++) {
            unsigned pa[4];
            pa[0] = h2u(__floats2half2_rn(sacc[2 * ks][0],     sacc[2 * ks][1]));
            pa[1] = h2u(__floats2half2_rn(sacc[2 * ks][2],     sacc[2 * ks][3]));
            pa[2] = h2u(__floats2half2_rn(sacc[2 * ks + 1][0], sacc[2 * ks + 1][1]));
            pa[3] = h2u(__floats2half2_rn(sacc[2 * ks + 1][2], sacc[2 * ks + 1][3]));
            #pragma unroll
            for (int dp = 0; dp < 4; dp++) {
                unsigned bf[4];
                ldm4(bf, saddr(&Vs[(dp * 16 + (lane & 7) + ((lane & 16) >> 1)) * 72
                                    + ks * 16 + (lane & 8)]));
                mma16(oacc[dp * 2],     pa, bf[0], bf[1]);
                mma16(oacc[dp * 2 + 1], pa, bf[2], bf[3]);
            }
        }
        __syncthreads();
    }

    const float li0 = 1.f / lrow0, li1 = 1.f / lrow1;
    #pragma unroll
    for (int n = 0; n < 8; n++) {
        int c = hd * 64 + n * 8 + 2 * tg;
        size_t base = (size_t)c * NTOK + t0 + m0 + g;
        hout[base]            = __float2half(oacc[n][0] * li0);
        hout[base + NTOK]     = __float2half(oacc[n][1] * li0);
        hout[base + 8]        = __float2half(oacc[n][2] * li1);
        hout[base + NTOK + 8] = __float2half(oacc[n][3] * li1);
    }
}

// ---------------------------------------------------------------------------
extern "C" void kernel_launch(void* const* d_in, const int* in_sizes, int n_in,
                              void* d_out, int out_size)
{
    const float* x      = (const float*)d_in[0];
    const float* gamma  = (const float*)d_in[1];
    const float* beta   = (const float*)d_in[2];
    const float* w_qkv  = (const float*)d_in[3];
    const float* w_proj = (const float*)d_in[4];
    const float* b_proj = (const float*)d_in[5];
    float* out = (float*)d_out;

    __half *xn, *qkv, *h, *wq, *wp;
    cudaGetSymbolAddress((void**)&xn,  g_xn);
    cudaGetSymbolAddress((void**)&qkv, g_qkv);
    cudaGetSymbolAddress((void**)&h,   g_h);
    cudaGetSymbolAddress((void**)&wq,  g_wq);
    cudaGetSymbolAddress((void**)&wp,  g_wp);

    cudaFuncSetAttribute(attn_h, cudaFuncAttributeMaxDynamicSharedMemorySize, ATT_SMEM);
    cudaFuncSetAttribute(gemm_h<false>, cudaFuncAttributeMaxDynamicSharedMemorySize, GEMM_SMEM);
    cudaFuncSetAttribute(gemm_h<true>,  cudaFuncAttributeMaxDynamicSharedMemorySize, GEMM_SMEM);

    cvt_h<<<96, 256>>>(w_qkv, wq, 3 * CDIM * CDIM);
    cvt_h<<<32, 256>>>(w_proj, wp, CDIM * CDIM);
    gn_stats<<<128, 256>>>(x);
    gn_apply<<<256, 256>>>(x, gamma, beta, xn);
    gemm_h<false><<<dim3(NTOK / 128, 768 / 64), 256, GEMM_SMEM>>>(
        wq, xn, qkv, 768, NTOK, CDIM, nullptr, nullptr);
    attn_h<<<dim3(NTOK / 64, 4), 128, ATT_SMEM>>>(qkv, h);
    gemm_h<true><<<dim3(NTOK / 128, CDIM / 64), 256, GEMM_SMEM>>>(
        wp, h, out, CDIM, NTOK, CDIM, b_proj, x);
}